// round 1
// baseline (speedup 1.0000x reference)
#include <cuda_runtime.h>
#include <math.h>
#include <stdint.h>

// Problem dims
#define BB 2048
#define TT 64
#define DD 512
#define SS 256
#define PP 11
#define HH1 384
#define NCAT 1152   // HH1 + 3*SS

// Scratch layout (floats) in one __device__ array (no cudaMalloc allowed)
#define OFF_F   ((size_t)0)                          // [B*T, NCAT]
#define SZ_F    ((size_t)BB * TT * NCAT)             // 150,994,944
#define OFF_ZH  (OFF_F + SZ_F)                       // [B, NCAT]
#define SZ_ZH   ((size_t)BB * NCAT)
#define OFF_H   (OFF_ZH + SZ_ZH)                     // [B, S]
#define SZ_H    ((size_t)BB * SS)
#define OFF_WF  (OFF_H + SZ_H)                       // [NCAT, D]
#define SZ_WF   ((size_t)NCAT * DD)
#define OFF_BF  (OFF_WF + SZ_WF)                     // [NCAT]
#define SZ_BF   ((size_t)1280)
#define OFF_WH  (OFF_BF + SZ_BF)                     // [NCAT, S]
#define SZ_WH   ((size_t)NCAT * SS)
#define SCRATCH_TOTAL (OFF_WH + SZ_WH)

__device__ float g_scratch[SCRATCH_TOTAL];

// ---------------------------------------------------------------------------
// Pack kernel: build fused weight matrices + init h
//   Wf[n][k] (n<H1 -> W1[n][0:512], else W_ih[n-H1][0:512])
//   bf[n]    (b1 / b_ih)
//   Wh[n][k] (n<H1 -> W1[n][512:768], else W_hh[n-H1][:])
//   h[b][s] = h0[s]
// ---------------------------------------------------------------------------
__global__ void pack_kernel(const float* __restrict__ W1,
                            const float* __restrict__ b1,
                            const float* __restrict__ W_ih,
                            const float* __restrict__ b_ih,
                            const float* __restrict__ W_hh,
                            const float* __restrict__ h0,
                            float* __restrict__ Wf,
                            float* __restrict__ bf,
                            float* __restrict__ Wh,
                            float* __restrict__ h)
{
    int i = blockIdx.x * blockDim.x + threadIdx.x;
    if (i < NCAT * DD) {
        int n = i / DD, k = i % DD;
        Wf[i] = (n < HH1) ? W1[n * (DD + SS) + k]
                          : W_ih[(n - HH1) * (DD + 1) + k];
    }
    if (i < NCAT * SS) {
        int n = i / SS, k = i % SS;
        Wh[i] = (n < HH1) ? W1[n * (DD + SS) + DD + k]
                          : W_hh[(n - HH1) * SS + k];
    }
    if (i < NCAT) bf[i] = (i < HH1) ? b1[i] : b_ih[i - HH1];
    if (i < BB * SS) h[i] = h0[i % SS];
}

// ---------------------------------------------------------------------------
// Tiled SGEMM (TN form): C[m][n] = sum_k A[m][k] * W[n][k] (+ bias[n])
// Both operands K-major (row-major with K contiguous). BM == BN required.
// 256 threads, (BM/TM)x(BN/TN) = 16x16 thread grid.
// ---------------------------------------------------------------------------
template <int BM, int BN, int BK, int TM, int TN>
__global__ void __launch_bounds__(256)
sgemm_tn(int M, int N, int K,
         const float* __restrict__ A,
         const float* __restrict__ W,
         const float* __restrict__ bias,
         float* __restrict__ C)
{
    static_assert(BM == BN, "load mapping assumes BM==BN");
    static_assert(256 * 4 == BM * BK, "one vectorized load per thread per tile");
    __shared__ float As[BK][BM];
    __shared__ float Bs[BK][BN];

    const int n0 = blockIdx.x * BN;
    const int m0 = blockIdx.y * BM;
    const int tid = threadIdx.x;

    const int kv = BK / 4;
    const int lrow = tid / kv;          // row within tile (covers BM == BN)
    const int lcol = (tid % kv) * 4;    // k offset within BK

    const int tr = (tid / (BN / TN)) * TM;
    const int tc = (tid % (BN / TN)) * TN;

    float acc[TM][TN];
#pragma unroll
    for (int i = 0; i < TM; i++)
#pragma unroll
        for (int j = 0; j < TN; j++) acc[i][j] = 0.0f;

    const float* Ag = A + (size_t)(m0 + lrow) * K + lcol;
    const float* Wg = W + (size_t)(n0 + lrow) * K + lcol;

    for (int k0 = 0; k0 < K; k0 += BK) {
        float4 a4 = *(const float4*)(Ag + k0);
        float4 b4 = *(const float4*)(Wg + k0);
        As[lcol + 0][lrow] = a4.x; As[lcol + 1][lrow] = a4.y;
        As[lcol + 2][lrow] = a4.z; As[lcol + 3][lrow] = a4.w;
        Bs[lcol + 0][lrow] = b4.x; Bs[lcol + 1][lrow] = b4.y;
        Bs[lcol + 2][lrow] = b4.z; Bs[lcol + 3][lrow] = b4.w;
        __syncthreads();

#pragma unroll
        for (int k = 0; k < BK; k++) {
            float rm[TM], rn[TN];
#pragma unroll
            for (int i = 0; i < TM; i++) rm[i] = As[k][tr + i];
#pragma unroll
            for (int j = 0; j < TN; j++) rn[j] = Bs[k][tc + j];
#pragma unroll
            for (int i = 0; i < TM; i++)
#pragma unroll
                for (int j = 0; j < TN; j++)
                    acc[i][j] = fmaf(rm[i], rn[j], acc[i][j]);
        }
        __syncthreads();
    }

#pragma unroll
    for (int i = 0; i < TM; i++) {
        const size_t row = (size_t)(m0 + tr + i);
#pragma unroll
        for (int j = 0; j < TN; j += 4) {
            float4 v;
            v.x = acc[i][j + 0]; v.y = acc[i][j + 1];
            v.z = acc[i][j + 2]; v.w = acc[i][j + 3];
            if (bias != nullptr) {
                v.x += bias[n0 + tc + j + 0];
                v.y += bias[n0 + tc + j + 1];
                v.z += bias[n0 + tc + j + 2];
                v.w += bias[n0 + tc + j + 3];
            }
            *(float4*)(C + row * N + n0 + tc + j) = v;
        }
    }
}

// ---------------------------------------------------------------------------
// Per-step fusion: relu-combine -> logits -> gumbel softmax -> pos -> GRU
// One block per batch row, 256 threads.
// ---------------------------------------------------------------------------
__global__ void __launch_bounds__(256)
step_kernel(int t,
            const float* __restrict__ u,
            const float* __restrict__ W2,
            const float* __restrict__ b2,
            const float* __restrict__ temp_ptr,
            const float* __restrict__ W_ih,
            const float* __restrict__ b_hh,
            const float* __restrict__ F,
            const float* __restrict__ Zh,
            float* __restrict__ h,
            float* __restrict__ out_pos,
            float* __restrict__ out_states,
            float* __restrict__ out_hfinal)
{
    const int b = blockIdx.x;
    const int tid = threadIdx.x;
    const int warp = tid >> 5, lane = tid & 31;
    const size_t bt = (size_t)b * TT + t;

    __shared__ float sh_hidden[HH1];
    __shared__ float sh_logits[PP];
    __shared__ float sh_pos;

    const float* Frow = F + bt * NCAT;
    const float* Zrow = Zh + (size_t)b * NCAT;

    // hidden = relu(F_feat + Zh_h) (bias already folded into F)
    for (int j = tid; j < HH1; j += 256)
        sh_hidden[j] = fmaxf(Frow[j] + Zrow[j], 0.0f);
    __syncthreads();

    // logits[p] = hidden . W2[p] + b2[p]; one warp per logit (wrap for 8..10)
    for (int p = warp; p < PP; p += 8) {
        const float* w2 = W2 + p * HH1;
        float s = 0.0f;
        for (int k = lane; k < HH1; k += 32) s = fmaf(sh_hidden[k], w2[k], s);
#pragma unroll
        for (int off = 16; off > 0; off >>= 1)
            s += __shfl_xor_sync(0xffffffffu, s, off);
        if (lane == 0) sh_logits[p] = s + b2[p];
    }
    __syncthreads();

    // gumbel softmax + expected position (warp 0)
    if (warp == 0) {
        float temp = *temp_ptr;
        float val = -INFINITY;
        if (lane < PP) {
            float uu = u[bt * PP + lane];
            float g = -logf(-logf(uu + 1e-20f) + 1e-20f);
            val = (sh_logits[lane] + g) / temp;
        }
        float m = val;
#pragma unroll
        for (int off = 16; off > 0; off >>= 1)
            m = fmaxf(m, __shfl_xor_sync(0xffffffffu, m, off));
        float e = expf(val - m);                 // lanes >= P: exp(-inf) = 0
        float s = e;
        float w = (lane < PP) ? e * (float)lane : 0.0f;
#pragma unroll
        for (int off = 16; off > 0; off >>= 1) {
            s += __shfl_xor_sync(0xffffffffu, s, off);
            w += __shfl_xor_sync(0xffffffffu, w, off);
        }
        if (lane == 0) {
            float pos = w / s;
            sh_pos = pos;
            out_pos[bt] = pos;
        }
    }
    __syncthreads();
    const float pos = sh_pos;

    // GRU update, one thread per state unit
    const int j = tid;   // 0..255 == SS
    // gi = F_gi (feat part + b_ih) + pos * W_ih[:, 512]
    float gi_r = Frow[HH1 + j]          + pos * W_ih[(size_t)(j)          * (DD + 1) + DD];
    float gi_z = Frow[HH1 + SS + j]     + pos * W_ih[(size_t)(SS + j)     * (DD + 1) + DD];
    float gi_n = Frow[HH1 + 2 * SS + j] + pos * W_ih[(size_t)(2 * SS + j) * (DD + 1) + DD];
    float gh_r = Zrow[HH1 + j]          + b_hh[j];
    float gh_z = Zrow[HH1 + SS + j]     + b_hh[SS + j];
    float gh_n = Zrow[HH1 + 2 * SS + j] + b_hh[2 * SS + j];

    float r = 1.0f / (1.0f + expf(-(gi_r + gh_r)));
    float z = 1.0f / (1.0f + expf(-(gi_z + gh_z)));
    float n = tanhf(gi_n + r * gh_n);
    float hold = h[(size_t)b * SS + j];
    float hnew = (1.0f - z) * n + z * hold;

    h[(size_t)b * SS + j] = hnew;
    out_states[bt * SS + j] = hnew;
    if (t == TT - 1) out_hfinal[(size_t)b * SS + j] = hnew;
}

// ---------------------------------------------------------------------------
extern "C" void kernel_launch(void* const* d_in, const int* in_sizes, int n_in,
                              void* d_out, int out_size)
{
    const float* price = (const float*)d_in[0];
    const float* u     = (const float*)d_in[1];
    const float* W1    = (const float*)d_in[2];
    const float* b1    = (const float*)d_in[3];
    const float* W2    = (const float*)d_in[4];
    const float* b2    = (const float*)d_in[5];
    const float* temp  = (const float*)d_in[6];
    const float* W_ih  = (const float*)d_in[7];
    const float* b_ih  = (const float*)d_in[8];
    const float* W_hh  = (const float*)d_in[9];
    const float* b_hh  = (const float*)d_in[10];
    const float* h0    = (const float*)d_in[11];

    float* scratch = nullptr;
    cudaGetSymbolAddress((void**)&scratch, g_scratch);
    float* F  = scratch + OFF_F;
    float* Zh = scratch + OFF_ZH;
    float* h  = scratch + OFF_H;
    float* Wf = scratch + OFF_WF;
    float* bf = scratch + OFF_BF;
    float* Wh = scratch + OFF_WH;

    float* out        = (float*)d_out;
    float* out_pos    = out;                                  // [B, T]
    float* out_states = out + (size_t)BB * TT;                // [B, T, S]
    float* out_hf     = out_states + (size_t)BB * TT * SS;    // [B, S]

    // 1. pack fused weights + init h
    {
        int total = NCAT * DD;   // largest range
        pack_kernel<<<(total + 255) / 256, 256>>>(W1, b1, W_ih, b_ih, W_hh, h0,
                                                  Wf, bf, Wh, h);
    }

    // 2. big parallel GEMM: F[B*T, 1152] = feats @ Wf^T + bf
    {
        dim3 grid(NCAT / 128, (BB * TT) / 128);   // (9, 1024)
        sgemm_tn<128, 128, 8, 8, 8><<<grid, 256>>>(BB * TT, NCAT, DD,
                                                   price, Wf, bf, F);
    }

    // 3. sequential recurrence
    for (int t = 0; t < TT; t++) {
        dim3 grid(NCAT / 64, BB / 64);            // (18, 32) = 576 blocks
        sgemm_tn<64, 64, 16, 4, 4><<<grid, 256>>>(BB, NCAT, SS,
                                                  h, Wh, nullptr, Zh);
        step_kernel<<<BB, 256>>>(t, u, W2, b2, temp, W_ih, b_hh,
                                 F, Zh, h, out_pos, out_states, out_hf);
    }
}

// round 2
// speedup vs baseline: 1.4823x; 1.4823x over previous
#include <cuda_runtime.h>
#include <math.h>
#include <stdint.h>

// Problem dims
#define BB 2048
#define TT 64
#define DD 512
#define SS 256
#define PP 11
#define HH1 384
#define NCAT 1152   // HH1 + 3*SS

// Scratch layout (floats) in one __device__ array (no cudaMalloc allowed)
#define OFF_F   ((size_t)0)                          // [B*T, NCAT]
#define SZ_F    ((size_t)BB * TT * NCAT)
#define OFF_ZH  (OFF_F + SZ_F)                       // [B, NCAT]
#define SZ_ZH   ((size_t)BB * NCAT)
#define OFF_H   (OFF_ZH + SZ_ZH)                     // [B, S]
#define SZ_H    ((size_t)BB * SS)
#define OFF_WF  (OFF_H + SZ_H)                       // [NCAT, D]
#define SZ_WF   ((size_t)NCAT * DD)
#define OFF_BF  (OFF_WF + SZ_WF)                     // [NCAT]
#define SZ_BF   ((size_t)1280)
#define OFF_WH  (OFF_BF + SZ_BF)                     // [NCAT, S]
#define SZ_WH   ((size_t)NCAT * SS)
#define SCRATCH_TOTAL (OFF_WH + SZ_WH)

__device__ float g_scratch[SCRATCH_TOTAL];

// ---------------------------------------------------------------------------
// Pack kernel: fused weights + init h
// ---------------------------------------------------------------------------
__global__ void pack_kernel(const float* __restrict__ W1,
                            const float* __restrict__ b1,
                            const float* __restrict__ W_ih,
                            const float* __restrict__ b_ih,
                            const float* __restrict__ W_hh,
                            const float* __restrict__ h0,
                            float* __restrict__ Wf,
                            float* __restrict__ bf,
                            float* __restrict__ Wh,
                            float* __restrict__ h)
{
    int i = blockIdx.x * blockDim.x + threadIdx.x;
    if (i < NCAT * DD) {
        int n = i / DD, k = i % DD;
        Wf[i] = (n < HH1) ? W1[n * (DD + SS) + k]
                          : W_ih[(n - HH1) * (DD + 1) + k];
    }
    if (i < NCAT * SS) {
        int n = i / SS, k = i % SS;
        Wh[i] = (n < HH1) ? W1[n * (DD + SS) + DD + k]
                          : W_hh[(n - HH1) * SS + k];
    }
    if (i < NCAT) bf[i] = (i < HH1) ? b1[i] : b_ih[i - HH1];
    if (i < BB * SS) h[i] = h0[i % SS];
}

// ---------------------------------------------------------------------------
// TF32x3 tensor-core GEMM (TN): C[m][n] = sum_k A[m][k]*W[n][k] (+bias[n])
// fp32-accurate via hi/lo split: a*b ~= ah*bh + al*bh + ah*bl.
// BM=BN=128, BK=16, 256 threads = 8 warps (4m x 2n), warp tile 32x64.
// ---------------------------------------------------------------------------
__device__ __forceinline__ unsigned f2tf32(float x) {
    unsigned r;
    asm("cvt.rna.tf32.f32 %0, %1;" : "=r"(r) : "f"(x));
    return r;
}

__device__ __forceinline__ void mma8(float* c, const unsigned* a,
                                     unsigned b0, unsigned b1) {
    asm volatile(
        "mma.sync.aligned.m16n8k8.row.col.f32.tf32.tf32.f32 "
        "{%0,%1,%2,%3}, {%4,%5,%6,%7}, {%8,%9}, {%0,%1,%2,%3};\n"
        : "+f"(c[0]), "+f"(c[1]), "+f"(c[2]), "+f"(c[3])
        : "r"(a[0]), "r"(a[1]), "r"(a[2]), "r"(a[3]), "r"(b0), "r"(b1));
}

#define BKP 20   // padded k-stride (bank-conflict-free for fragment loads)

__global__ void __launch_bounds__(256, 2)
gemm_tf32x3(int M, int N, int K,
            const float* __restrict__ A,
            const float* __restrict__ W,
            const float* __restrict__ bias,
            float* __restrict__ C)
{
    __shared__ float As_hi[128][BKP];
    __shared__ float As_lo[128][BKP];
    __shared__ float Bs_hi[128][BKP];
    __shared__ float Bs_lo[128][BKP];

    const int tid  = threadIdx.x;
    const int warp = tid >> 5, lane = tid & 31;
    const int g = lane >> 2, t = lane & 3;
    const int wm = warp >> 1, wn = warp & 1;   // 4 x 2 warp grid

    const int n0 = blockIdx.x * 128;
    const int m0 = blockIdx.y * 128;

    const int lrow = tid >> 2;           // 0..63
    const int lcol = (tid & 3) * 4;      // 0,4,8,12

    float4 pa[2], pb[2];

    // preload first tile
#pragma unroll
    for (int i = 0; i < 2; i++) {
        pa[i] = *(const float4*)(A + (size_t)(m0 + lrow + i * 64) * K + lcol);
        pb[i] = *(const float4*)(W + (size_t)(n0 + lrow + i * 64) * K + lcol);
    }

    float acc[2][8][4];
#pragma unroll
    for (int mt = 0; mt < 2; mt++)
#pragma unroll
        for (int nt = 0; nt < 8; nt++)
#pragma unroll
            for (int r = 0; r < 4; r++) acc[mt][nt][r] = 0.0f;

    for (int k0 = 0; k0 < K; k0 += 16) {
        // store current regs -> smem (hi/lo split)
#pragma unroll
        for (int i = 0; i < 2; i++) {
            int row = lrow + i * 64;
            float4 v = pa[i], h4, l4;
            h4.x = __uint_as_float(f2tf32(v.x)); l4.x = v.x - h4.x;
            h4.y = __uint_as_float(f2tf32(v.y)); l4.y = v.y - h4.y;
            h4.z = __uint_as_float(f2tf32(v.z)); l4.z = v.z - h4.z;
            h4.w = __uint_as_float(f2tf32(v.w)); l4.w = v.w - h4.w;
            *(float4*)&As_hi[row][lcol] = h4;
            *(float4*)&As_lo[row][lcol] = l4;
            v = pb[i];
            h4.x = __uint_as_float(f2tf32(v.x)); l4.x = v.x - h4.x;
            h4.y = __uint_as_float(f2tf32(v.y)); l4.y = v.y - h4.y;
            h4.z = __uint_as_float(f2tf32(v.z)); l4.z = v.z - h4.z;
            h4.w = __uint_as_float(f2tf32(v.w)); l4.w = v.w - h4.w;
            *(float4*)&Bs_hi[row][lcol] = h4;
            *(float4*)&Bs_lo[row][lcol] = l4;
        }
        __syncthreads();

        // prefetch next tile (overlaps with compute below)
        if (k0 + 16 < K) {
#pragma unroll
            for (int i = 0; i < 2; i++) {
                pa[i] = *(const float4*)(A + (size_t)(m0 + lrow + i * 64) * K + k0 + 16 + lcol);
                pb[i] = *(const float4*)(W + (size_t)(n0 + lrow + i * 64) * K + k0 + 16 + lcol);
            }
        }

        // compute: two k8 slabs
#pragma unroll
        for (int kk = 0; kk < 16; kk += 8) {
            unsigned ah[2][4], al[2][4];
#pragma unroll
            for (int mt = 0; mt < 2; mt++) {
                int mb = wm * 32 + mt * 16;
                ah[mt][0] = __float_as_uint(As_hi[mb + g    ][kk + t    ]);
                ah[mt][1] = __float_as_uint(As_hi[mb + g + 8][kk + t    ]);
                ah[mt][2] = __float_as_uint(As_hi[mb + g    ][kk + t + 4]);
                ah[mt][3] = __float_as_uint(As_hi[mb + g + 8][kk + t + 4]);
                al[mt][0] = __float_as_uint(As_lo[mb + g    ][kk + t    ]);
                al[mt][1] = __float_as_uint(As_lo[mb + g + 8][kk + t    ]);
                al[mt][2] = __float_as_uint(As_lo[mb + g    ][kk + t + 4]);
                al[mt][3] = __float_as_uint(As_lo[mb + g + 8][kk + t + 4]);
            }
#pragma unroll
            for (int nt = 0; nt < 8; nt++) {
                int nb = wn * 64 + nt * 8;
                unsigned bh0 = __float_as_uint(Bs_hi[nb + g][kk + t    ]);
                unsigned bh1 = __float_as_uint(Bs_hi[nb + g][kk + t + 4]);
                unsigned bl0 = __float_as_uint(Bs_lo[nb + g][kk + t    ]);
                unsigned bl1 = __float_as_uint(Bs_lo[nb + g][kk + t + 4]);
#pragma unroll
                for (int mt = 0; mt < 2; mt++) {
                    mma8(acc[mt][nt], al[mt], bh0, bh1);
                    mma8(acc[mt][nt], ah[mt], bl0, bl1);
                    mma8(acc[mt][nt], ah[mt], bh0, bh1);
                }
            }
        }
        __syncthreads();
    }

    // epilogue
#pragma unroll
    for (int mt = 0; mt < 2; mt++) {
        int r0 = m0 + wm * 32 + mt * 16 + g;
#pragma unroll
        for (int nt = 0; nt < 8; nt++) {
            int col = n0 + wn * 64 + nt * 8 + 2 * t;
            float bv0 = 0.0f, bv1 = 0.0f;
            if (bias != nullptr) { bv0 = bias[col]; bv1 = bias[col + 1]; }
            float2 v;
            v.x = acc[mt][nt][0] + bv0; v.y = acc[mt][nt][1] + bv1;
            *(float2*)&C[(size_t)r0 * N + col] = v;
            v.x = acc[mt][nt][2] + bv0; v.y = acc[mt][nt][3] + bv1;
            *(float2*)&C[(size_t)(r0 + 8) * N + col] = v;
        }
    }
}

// ---------------------------------------------------------------------------
// Per-step fusion: relu-combine -> logits -> gumbel softmax -> pos -> GRU
// ---------------------------------------------------------------------------
__global__ void __launch_bounds__(256)
step_kernel(int t,
            const float* __restrict__ u,
            const float* __restrict__ W2,
            const float* __restrict__ b2,
            const float* __restrict__ temp_ptr,
            const float* __restrict__ W_ih,
            const float* __restrict__ b_hh,
            const float* __restrict__ F,
            const float* __restrict__ Zh,
            float* __restrict__ h,
            float* __restrict__ out_pos,
            float* __restrict__ out_states,
            float* __restrict__ out_hfinal)
{
    const int b = blockIdx.x;
    const int tid = threadIdx.x;
    const int warp = tid >> 5, lane = tid & 31;
    const size_t bt = (size_t)b * TT + t;

    __shared__ float sh_hidden[HH1];
    __shared__ float sh_logits[PP];
    __shared__ float sh_pos;

    const float* Frow = F + bt * NCAT;
    const float* Zrow = Zh + (size_t)b * NCAT;

    for (int j = tid; j < HH1; j += 256)
        sh_hidden[j] = fmaxf(Frow[j] + Zrow[j], 0.0f);
    __syncthreads();

    for (int p = warp; p < PP; p += 8) {
        const float* w2 = W2 + p * HH1;
        float s = 0.0f;
        for (int k = lane; k < HH1; k += 32) s = fmaf(sh_hidden[k], w2[k], s);
#pragma unroll
        for (int off = 16; off > 0; off >>= 1)
            s += __shfl_xor_sync(0xffffffffu, s, off);
        if (lane == 0) sh_logits[p] = s + b2[p];
    }
    __syncthreads();

    if (warp == 0) {
        float temp = *temp_ptr;
        float val = -INFINITY;
        if (lane < PP) {
            float uu = u[bt * PP + lane];
            float gmb = -logf(-logf(uu + 1e-20f) + 1e-20f);
            val = (sh_logits[lane] + gmb) / temp;
        }
        float m = val;
#pragma unroll
        for (int off = 16; off > 0; off >>= 1)
            m = fmaxf(m, __shfl_xor_sync(0xffffffffu, m, off));
        float e = expf(val - m);
        float s = e;
        float w = (lane < PP) ? e * (float)lane : 0.0f;
#pragma unroll
        for (int off = 16; off > 0; off >>= 1) {
            s += __shfl_xor_sync(0xffffffffu, s, off);
            w += __shfl_xor_sync(0xffffffffu, w, off);
        }
        if (lane == 0) {
            float pos = w / s;
            sh_pos = pos;
            out_pos[bt] = pos;
        }
    }
    __syncthreads();
    const float pos = sh_pos;

    const int j = tid;   // 0..255 == SS
    float gi_r = Frow[HH1 + j]          + pos * W_ih[(size_t)(j)          * (DD + 1) + DD];
    float gi_z = Frow[HH1 + SS + j]     + pos * W_ih[(size_t)(SS + j)     * (DD + 1) + DD];
    float gi_n = Frow[HH1 + 2 * SS + j] + pos * W_ih[(size_t)(2 * SS + j) * (DD + 1) + DD];
    float gh_r = Zrow[HH1 + j]          + b_hh[j];
    float gh_z = Zrow[HH1 + SS + j]     + b_hh[SS + j];
    float gh_n = Zrow[HH1 + 2 * SS + j] + b_hh[2 * SS + j];

    float r = 1.0f / (1.0f + expf(-(gi_r + gh_r)));
    float z = 1.0f / (1.0f + expf(-(gi_z + gh_z)));
    float n = tanhf(gi_n + r * gh_n);
    float hold = h[(size_t)b * SS + j];
    float hnew = (1.0f - z) * n + z * hold;

    h[(size_t)b * SS + j] = hnew;
    out_states[bt * SS + j] = hnew;
    if (t == TT - 1) out_hfinal[(size_t)b * SS + j] = hnew;
}

// ---------------------------------------------------------------------------
extern "C" void kernel_launch(void* const* d_in, const int* in_sizes, int n_in,
                              void* d_out, int out_size)
{
    const float* price = (const float*)d_in[0];
    const float* u     = (const float*)d_in[1];
    const float* W1    = (const float*)d_in[2];
    const float* b1    = (const float*)d_in[3];
    const float* W2    = (const float*)d_in[4];
    const float* b2    = (const float*)d_in[5];
    const float* temp  = (const float*)d_in[6];
    const float* W_ih  = (const float*)d_in[7];
    const float* b_ih  = (const float*)d_in[8];
    const float* W_hh  = (const float*)d_in[9];
    const float* b_hh  = (const float*)d_in[10];
    const float* h0    = (const float*)d_in[11];

    float* scratch = nullptr;
    cudaGetSymbolAddress((void**)&scratch, g_scratch);
    float* F  = scratch + OFF_F;
    float* Zh = scratch + OFF_ZH;
    float* h  = scratch + OFF_H;
    float* Wf = scratch + OFF_WF;
    float* bf = scratch + OFF_BF;
    float* Wh = scratch + OFF_WH;

    float* out        = (float*)d_out;
    float* out_pos    = out;                                  // [B, T]
    float* out_states = out + (size_t)BB * TT;                // [B, T, S]
    float* out_hf     = out_states + (size_t)BB * TT * SS;    // [B, S]

    // 1. pack fused weights + init h
    {
        int total = NCAT * DD;
        pack_kernel<<<(total + 255) / 256, 256>>>(W1, b1, W_ih, b_ih, W_hh, h0,
                                                  Wf, bf, Wh, h);
    }

    // 2. big parallel GEMM: F[B*T, 1152] = feats @ Wf^T + bf  (tensor cores)
    {
        dim3 grid(NCAT / 128, (BB * TT) / 128);   // (9, 1024)
        gemm_tf32x3<<<grid, 256>>>(BB * TT, NCAT, DD, price, Wf, bf, F);
    }

    // 3. sequential recurrence
    for (int t = 0; t < TT; t++) {
        dim3 grid(NCAT / 128, BB / 128);          // (9, 16) = 144 blocks
        gemm_tf32x3<<<grid, 256>>>(BB, NCAT, SS, h, Wh, nullptr, Zh);
        step_kernel<<<BB, 256>>>(t, u, W2, b2, temp, W_ih, b_hh,
                                 F, Zh, h, out_pos, out_states, out_hf);
    }
}

// round 3
// speedup vs baseline: 2.2146x; 1.4940x over previous
#include <cuda_runtime.h>
#include <cuda_bf16.h>
#include <math.h>
#include <stdint.h>

// Problem dims
#define BB 2048
#define TT 64
#define DD 512
#define SS 256
#define PP 11
#define HH1 384
#define NCAT 1152   // HH1 + 3*SS

// Scratch layout (floats) in one __device__ array (no cudaMalloc allowed)
#define OFF_F    ((size_t)0)                          // [B*T, NCAT]
#define SZ_F     ((size_t)BB * TT * NCAT)
#define OFF_ZH   (OFF_F + SZ_F)                       // [B, NCAT]
#define SZ_ZH    ((size_t)BB * NCAT)
#define OFF_H    (OFF_ZH + SZ_ZH)                     // [B, S]
#define SZ_H     ((size_t)BB * SS)
#define OFF_WF   (OFF_H + SZ_H)                       // [NCAT, D]
#define SZ_WF    ((size_t)NCAT * DD)
#define OFF_BF   (OFF_WF + SZ_WF)                     // [NCAT]
#define SZ_BF    ((size_t)1280)
#define OFF_WH   (OFF_BF + SZ_BF)                     // [NCAT, S]
#define SZ_WH    ((size_t)NCAT * SS)
#define OFF_WPOS (OFF_WH + SZ_WH)                     // [3*S]
#define SZ_WPOS  ((size_t)768)
#define SCRATCH_TOTAL (OFF_WPOS + SZ_WPOS)

__device__ float g_scratch[SCRATCH_TOTAL];

// ---------------------------------------------------------------------------
// Pack kernel: fused weights + init h + contiguous position column of W_ih
// ---------------------------------------------------------------------------
__global__ void pack_kernel(const float* __restrict__ W1,
                            const float* __restrict__ b1,
                            const float* __restrict__ W_ih,
                            const float* __restrict__ b_ih,
                            const float* __restrict__ W_hh,
                            const float* __restrict__ h0,
                            float* __restrict__ Wf,
                            float* __restrict__ bf,
                            float* __restrict__ Wh,
                            float* __restrict__ h,
                            float* __restrict__ wpos)
{
    int i = blockIdx.x * blockDim.x + threadIdx.x;
    if (i < NCAT * DD) {
        int n = i / DD, k = i % DD;
        Wf[i] = (n < HH1) ? W1[n * (DD + SS) + k]
                          : W_ih[(n - HH1) * (DD + 1) + k];
    }
    if (i < NCAT * SS) {
        int n = i / SS, k = i % SS;
        Wh[i] = (n < HH1) ? W1[n * (DD + SS) + DD + k]
                          : W_hh[(n - HH1) * SS + k];
    }
    if (i < NCAT) bf[i] = (i < HH1) ? b1[i] : b_ih[i - HH1];
    if (i < BB * SS) h[i] = h0[i % SS];
    if (i < 3 * SS) wpos[i] = W_ih[(size_t)i * (DD + 1) + DD];
}

// ---------------------------------------------------------------------------
// BF16x3 tensor-core GEMM (TN): C[m][n] = sum_k A[m][k]*W[n][k] (+bias[n])
// fp32-accurate via hi/lo split (Ootomo): a*b ~= ah*bh + al*bh + ah*bl.
// BM=BN=128, BK=16 (one m16n8k16 slab), 256 threads = 8 warps (4m x 2n),
// warp tile 32x64 = 2x8 fragments of m16n8.
// ---------------------------------------------------------------------------
__device__ __forceinline__ void split_pack(float x, float y,
                                           unsigned& hi, unsigned& lo) {
    __nv_bfloat162 h2 = __float22bfloat162_rn(make_float2(x, y));
    float rx = x - __bfloat162float(h2.x);
    float ry = y - __bfloat162float(h2.y);
    __nv_bfloat162 l2 = __float22bfloat162_rn(make_float2(rx, ry));
    hi = reinterpret_cast<unsigned&>(h2);
    lo = reinterpret_cast<unsigned&>(l2);
}

__device__ __forceinline__ void mma16(float* c, const unsigned* a,
                                      unsigned b0, unsigned b1) {
    asm volatile(
        "mma.sync.aligned.m16n8k16.row.col.f32.bf16.bf16.f32 "
        "{%0,%1,%2,%3}, {%4,%5,%6,%7}, {%8,%9}, {%0,%1,%2,%3};\n"
        : "+f"(c[0]), "+f"(c[1]), "+f"(c[2]), "+f"(c[3])
        : "r"(a[0]), "r"(a[1]), "r"(a[2]), "r"(a[3]), "r"(b0), "r"(b1));
}

#define KW 12   // padded u32 k-stride (8 used) -> conflict-free fragment loads

__global__ void __launch_bounds__(256, 2)
gemm_bf16x3(int M, int N, int K,
            const float* __restrict__ A,
            const float* __restrict__ W,
            const float* __restrict__ bias,
            float* __restrict__ C)
{
    __shared__ unsigned As_hi[128][KW];
    __shared__ unsigned As_lo[128][KW];
    __shared__ unsigned Bs_hi[128][KW];
    __shared__ unsigned Bs_lo[128][KW];

    const int tid  = threadIdx.x;
    const int warp = tid >> 5, lane = tid & 31;
    const int g = lane >> 2, t = lane & 3;
    const int wm = warp >> 1, wn = warp & 1;   // 4 x 2 warp grid

    const int n0 = blockIdx.x * 128;
    const int m0 = blockIdx.y * 128;

    const int lrow = tid >> 2;           // 0..63
    const int lcol = (tid & 3) * 4;      // float k offset: 0,4,8,12
    const int lc2  = (tid & 3) * 2;      // u32 k offset: 0,2,4,6

    float4 pa[2], pb[2];

    // preload first tile
#pragma unroll
    for (int i = 0; i < 2; i++) {
        pa[i] = *(const float4*)(A + (size_t)(m0 + lrow + i * 64) * K + lcol);
        pb[i] = *(const float4*)(W + (size_t)(n0 + lrow + i * 64) * K + lcol);
    }

    float acc[2][8][4];
#pragma unroll
    for (int mt = 0; mt < 2; mt++)
#pragma unroll
        for (int nt = 0; nt < 8; nt++)
#pragma unroll
            for (int r = 0; r < 4; r++) acc[mt][nt][r] = 0.0f;

    for (int k0 = 0; k0 < K; k0 += 16) {
        // split current regs -> smem hi/lo bf16 pairs
#pragma unroll
        for (int i = 0; i < 2; i++) {
            int row = lrow + i * 64;
            unsigned h0, l0, h1, l1;
            split_pack(pa[i].x, pa[i].y, h0, l0);
            split_pack(pa[i].z, pa[i].w, h1, l1);
            As_hi[row][lc2] = h0; As_hi[row][lc2 + 1] = h1;
            As_lo[row][lc2] = l0; As_lo[row][lc2 + 1] = l1;
            split_pack(pb[i].x, pb[i].y, h0, l0);
            split_pack(pb[i].z, pb[i].w, h1, l1);
            Bs_hi[row][lc2] = h0; Bs_hi[row][lc2 + 1] = h1;
            Bs_lo[row][lc2] = l0; Bs_lo[row][lc2 + 1] = l1;
        }
        __syncthreads();

        // prefetch next tile (overlaps with compute below)
        if (k0 + 16 < K) {
#pragma unroll
            for (int i = 0; i < 2; i++) {
                pa[i] = *(const float4*)(A + (size_t)(m0 + lrow + i * 64) * K + k0 + 16 + lcol);
                pb[i] = *(const float4*)(W + (size_t)(n0 + lrow + i * 64) * K + k0 + 16 + lcol);
            }
        }

        // fragments: one k16 slab
        unsigned ah[2][4], al[2][4];
#pragma unroll
        for (int mt = 0; mt < 2; mt++) {
            int mb = wm * 32 + mt * 16;
            ah[mt][0] = As_hi[mb + g    ][t];
            ah[mt][1] = As_hi[mb + g + 8][t];
            ah[mt][2] = As_hi[mb + g    ][t + 4];
            ah[mt][3] = As_hi[mb + g + 8][t + 4];
            al[mt][0] = As_lo[mb + g    ][t];
            al[mt][1] = As_lo[mb + g + 8][t];
            al[mt][2] = As_lo[mb + g    ][t + 4];
            al[mt][3] = As_lo[mb + g + 8][t + 4];
        }
#pragma unroll
        for (int nt = 0; nt < 8; nt++) {
            int nb = wn * 64 + nt * 8;
            unsigned bh0 = Bs_hi[nb + g][t];
            unsigned bh1 = Bs_hi[nb + g][t + 4];
            unsigned bl0 = Bs_lo[nb + g][t];
            unsigned bl1 = Bs_lo[nb + g][t + 4];
#pragma unroll
            for (int mt = 0; mt < 2; mt++) {
                mma16(acc[mt][nt], al[mt], bh0, bh1);
                mma16(acc[mt][nt], ah[mt], bl0, bl1);
                mma16(acc[mt][nt], ah[mt], bh0, bh1);
            }
        }
        __syncthreads();
    }

    // epilogue
#pragma unroll
    for (int mt = 0; mt < 2; mt++) {
        int r0 = m0 + wm * 32 + mt * 16 + g;
#pragma unroll
        for (int nt = 0; nt < 8; nt++) {
            int col = n0 + wn * 64 + nt * 8 + 2 * t;
            float bv0 = 0.0f, bv1 = 0.0f;
            if (bias != nullptr) { bv0 = bias[col]; bv1 = bias[col + 1]; }
            float2 v;
            v.x = acc[mt][nt][0] + bv0; v.y = acc[mt][nt][1] + bv1;
            *(float2*)&C[(size_t)r0 * N + col] = v;
            v.x = acc[mt][nt][2] + bv0; v.y = acc[mt][nt][3] + bv1;
            *(float2*)&C[(size_t)(r0 + 8) * N + col] = v;
        }
    }
}

// ---------------------------------------------------------------------------
// Per-step fusion: relu-combine -> logits -> gumbel softmax -> pos -> GRU
// ---------------------------------------------------------------------------
__global__ void __launch_bounds__(256)
step_kernel(int t,
            const float* __restrict__ u,
            const float* __restrict__ W2,
            const float* __restrict__ b2,
            const float* __restrict__ temp_ptr,
            const float* __restrict__ wpos,
            const float* __restrict__ b_hh,
            const float* __restrict__ F,
            const float* __restrict__ Zh,
            float* __restrict__ h,
            float* __restrict__ out_pos,
            float* __restrict__ out_states,
            float* __restrict__ out_hfinal)
{
    const int b = blockIdx.x;
    const int tid = threadIdx.x;
    const int warp = tid >> 5, lane = tid & 31;
    const size_t bt = (size_t)b * TT + t;

    __shared__ float sh_hidden[HH1];
    __shared__ float sh_logits[PP];
    __shared__ float sh_pos;

    const float* Frow = F + bt * NCAT;
    const float* Zrow = Zh + (size_t)b * NCAT;

    // hidden = relu(F_feat + Zh_h) -- float4 path (96 threads x 4)
    if (tid < 96) {
        float4 f = *(const float4*)(Frow + 4 * tid);
        float4 z = *(const float4*)(Zrow + 4 * tid);
        float4 r;
        r.x = fmaxf(f.x + z.x, 0.0f);
        r.y = fmaxf(f.y + z.y, 0.0f);
        r.z = fmaxf(f.z + z.z, 0.0f);
        r.w = fmaxf(f.w + z.w, 0.0f);
        *(float4*)&sh_hidden[4 * tid] = r;
    }
    __syncthreads();

    // logits[p] = hidden . W2[p] + b2[p]; one warp per logit, float4 dots
    for (int p = warp; p < PP; p += 8) {
        const float4* w4 = (const float4*)(W2 + p * HH1);
        const float4* h4 = (const float4*)sh_hidden;
        float s = 0.0f;
#pragma unroll
        for (int k = lane; k < 96; k += 32) {
            float4 w = w4[k], hh = h4[k];
            s = fmaf(w.x, hh.x, s);
            s = fmaf(w.y, hh.y, s);
            s = fmaf(w.z, hh.z, s);
            s = fmaf(w.w, hh.w, s);
        }
#pragma unroll
        for (int off = 16; off > 0; off >>= 1)
            s += __shfl_xor_sync(0xffffffffu, s, off);
        if (lane == 0) sh_logits[p] = s + b2[p];
    }
    __syncthreads();

    // gumbel softmax + expected position (warp 0)
    if (warp == 0) {
        float temp = *temp_ptr;
        float val = -INFINITY;
        if (lane < PP) {
            float uu = u[bt * PP + lane];
            float gmb = -logf(-logf(uu + 1e-20f) + 1e-20f);
            val = (sh_logits[lane] + gmb) / temp;
        }
        float m = val;
#pragma unroll
        for (int off = 16; off > 0; off >>= 1)
            m = fmaxf(m, __shfl_xor_sync(0xffffffffu, m, off));
        float e = expf(val - m);
        float s = e;
        float w = (lane < PP) ? e * (float)lane : 0.0f;
#pragma unroll
        for (int off = 16; off > 0; off >>= 1) {
            s += __shfl_xor_sync(0xffffffffu, s, off);
            w += __shfl_xor_sync(0xffffffffu, w, off);
        }
        if (lane == 0) {
            float pos = w / s;
            sh_pos = pos;
            out_pos[bt] = pos;
        }
    }
    __syncthreads();
    const float pos = sh_pos;

    // GRU update, one thread per state unit (all loads coalesced)
    const int j = tid;   // 0..255 == SS
    float hold = h[(size_t)b * SS + j];
    float gi_r = Frow[HH1 + j]          + pos * wpos[j];
    float gi_z = Frow[HH1 + SS + j]     + pos * wpos[SS + j];
    float gi_n = Frow[HH1 + 2 * SS + j] + pos * wpos[2 * SS + j];
    float gh_r = Zrow[HH1 + j]          + b_hh[j];
    float gh_z = Zrow[HH1 + SS + j]     + b_hh[SS + j];
    float gh_n = Zrow[HH1 + 2 * SS + j] + b_hh[2 * SS + j];

    float r = 1.0f / (1.0f + expf(-(gi_r + gh_r)));
    float z = 1.0f / (1.0f + expf(-(gi_z + gh_z)));
    float n = tanhf(gi_n + r * gh_n);
    float hnew = (1.0f - z) * n + z * hold;

    h[(size_t)b * SS + j] = hnew;
    out_states[bt * SS + j] = hnew;
    if (t == TT - 1) out_hfinal[(size_t)b * SS + j] = hnew;
}

// ---------------------------------------------------------------------------
extern "C" void kernel_launch(void* const* d_in, const int* in_sizes, int n_in,
                              void* d_out, int out_size)
{
    const float* price = (const float*)d_in[0];
    const float* u     = (const float*)d_in[1];
    const float* W1    = (const float*)d_in[2];
    const float* b1    = (const float*)d_in[3];
    const float* W2    = (const float*)d_in[4];
    const float* b2    = (const float*)d_in[5];
    const float* temp  = (const float*)d_in[6];
    const float* W_ih  = (const float*)d_in[7];
    const float* b_ih  = (const float*)d_in[8];
    const float* W_hh  = (const float*)d_in[9];
    const float* b_hh  = (const float*)d_in[10];
    const float* h0    = (const float*)d_in[11];

    float* scratch = nullptr;
    cudaGetSymbolAddress((void**)&scratch, g_scratch);
    float* F    = scratch + OFF_F;
    float* Zh   = scratch + OFF_ZH;
    float* h    = scratch + OFF_H;
    float* Wf   = scratch + OFF_WF;
    float* bf   = scratch + OFF_BF;
    float* Wh   = scratch + OFF_WH;
    float* wpos = scratch + OFF_WPOS;

    float* out        = (float*)d_out;
    float* out_pos    = out;                                  // [B, T]
    float* out_states = out + (size_t)BB * TT;                // [B, T, S]
    float* out_hf     = out_states + (size_t)BB * TT * SS;    // [B, S]

    // 1. pack fused weights + init h
    {
        int total = NCAT * DD;
        pack_kernel<<<(total + 255) / 256, 256>>>(W1, b1, W_ih, b_ih, W_hh, h0,
                                                  Wf, bf, Wh, h, wpos);
    }

    // 2. big parallel GEMM: F[B*T, 1152] = feats @ Wf^T + bf  (tensor cores)
    {
        dim3 grid(NCAT / 128, (BB * TT) / 128);   // (9, 1024)
        gemm_bf16x3<<<grid, 256>>>(BB * TT, NCAT, DD, price, Wf, bf, F);
    }

    // 3. sequential recurrence
    for (int t = 0; t < TT; t++) {
        dim3 grid(NCAT / 128, BB / 128);          // (9, 16) = 144 blocks
        gemm_bf16x3<<<grid, 256>>>(BB, NCAT, SS, h, Wh, nullptr, Zh);
        step_kernel<<<BB, 256>>>(t, u, W2, b2, temp, wpos, b_hh,
                                 F, Zh, h, out_pos, out_states, out_hf);
    }
}